// round 3
// baseline (speedup 1.0000x reference)
#include <cuda_runtime.h>

// DiscriminativeLoss: B=8, E=16, N=512*512, C<=32
// K0: zero scratch  K1: segment sums/counts (red.v4)  K2: hinged variance  K3: finalize

namespace {
constexpr int B_ = 8;
constexpr int E_ = 16;
constexpr int N_ = 512 * 512;     // 262144 pixels per batch
constexpr int N4_ = N_ / 4;       // 65536 float4 groups per batch
constexpr int N4SHIFT = 16;       // log2(N4_)
constexpr int CMAX = 32;
constexpr int CS = 33;            // label stride: labels 0..32 (0 = background)
constexpr float DVAR = 0.5f;
constexpr float TWO_DDIST = 3.0f; // 2 * DELTA_DIST
constexpr float GAMMA_ = 0.001f;
}

// Scratch accumulators (device globals — no allocation allowed)
__device__ float g_sums[B_ * CS * E_];   // per (b, label) embedding sums
__device__ float g_cnt[B_ * CS];         // per (b, label) pixel counts
__device__ float g_hinge[B_ * CS];       // per (b, label) hinged variance sums

__device__ __forceinline__ void red_add_v4(float* a, float x, float y, float z, float w) {
    asm volatile("red.global.add.v4.f32 [%0], {%1,%2,%3,%4};"
                 :: "l"(a), "f"(x), "f"(y), "f"(z), "f"(w) : "memory");
}
__device__ __forceinline__ void red_add(float* a, float v) {
    asm volatile("red.global.add.f32 [%0], %1;" :: "l"(a), "f"(v) : "memory");
}

__device__ __forceinline__ float wred(float v) {
#pragma unroll
    for (int o = 16; o; o >>= 1) v += __shfl_xor_sync(0xffffffffu, v, o);
    return v;
}

__global__ void k_zero() {
    int i = blockIdx.x * blockDim.x + threadIdx.x;
    if (i < B_ * CS * E_) g_sums[i] = 0.f;
    if (i < B_ * CS) { g_cnt[i] = 0.f; g_hinge[i] = 0.f; }
}

// ---------------- Pass 1: segment sums + counts ----------------
// Each thread owns 4 consecutive pixels (float4 across N). For each of the 4
// pixels, emits 4x red.global.add.v4.f32 (16 embedding dims) + 1 count red.
__global__ void __launch_bounds__(256) k_pass1(const float4* __restrict__ emb,
                                               const int4* __restrict__ mask) {
    int idx = blockIdx.x * blockDim.x + threadIdx.x;   // 0 .. B_*N4_-1
    int b = idx >> N4SHIFT;
    int n4 = idx & (N4_ - 1);
    int4 lab = mask[idx];
    const float4* ep = emb + (((size_t)b * E_) << N4SHIFT) + n4;

    bool vx = (lab.x > 0) & (lab.x <= CMAX);
    bool vy = (lab.y > 0) & (lab.y <= CMAX);
    bool vz = (lab.z > 0) & (lab.z <= CMAX);
    bool vw = (lab.w > 0) & (lab.w <= CMAX);
    float* bx = &g_sums[(b * CS + lab.x) * E_];
    float* by = &g_sums[(b * CS + lab.y) * E_];
    float* bz = &g_sums[(b * CS + lab.z) * E_];
    float* bw = &g_sums[(b * CS + lab.w) * E_];

#pragma unroll
    for (int g = 0; g < 4; g++) {
        float4 q0 = ep[(size_t)(4 * g + 0) << N4SHIFT];
        float4 q1 = ep[(size_t)(4 * g + 1) << N4SHIFT];
        float4 q2 = ep[(size_t)(4 * g + 2) << N4SHIFT];
        float4 q3 = ep[(size_t)(4 * g + 3) << N4SHIFT];
        if (vx) red_add_v4(bx + 4 * g, q0.x, q1.x, q2.x, q3.x);
        if (vy) red_add_v4(by + 4 * g, q0.y, q1.y, q2.y, q3.y);
        if (vz) red_add_v4(bz + 4 * g, q0.z, q1.z, q2.z, q3.z);
        if (vw) red_add_v4(bw + 4 * g, q0.w, q1.w, q2.w, q3.w);
    }
    if (vx) red_add(&g_cnt[b * CS + lab.x], 1.f);
    if (vy) red_add(&g_cnt[b * CS + lab.y], 1.f);
    if (vz) red_add(&g_cnt[b * CS + lab.z], 1.f);
    if (vw) red_add(&g_cnt[b * CS + lab.w], 1.f);
}

// ---------------- Pass 2: hinged variance ----------------
// Centers staged in shared with stride-17 padding (17 coprime to 32 banks:
// distinct labels -> distinct banks, equal labels -> broadcast).
__global__ void __launch_bounds__(256) k_pass2(const float4* __restrict__ emb,
                                               const int4* __restrict__ mask) {
    __shared__ float csh[CS * 17];
    int idx = blockIdx.x * blockDim.x + threadIdx.x;
    int b = idx >> N4SHIFT;   // constant per block (256 | 65536)

    for (int i = threadIdx.x; i < CS * E_; i += blockDim.x) {
        int l = i >> 4, e = i & 15;
        csh[l * 17 + e] = g_sums[(b * CS + l) * E_ + e] / fmaxf(g_cnt[b * CS + l], 1.f);
    }
    __syncthreads();

    int n4 = idx & (N4_ - 1);
    int4 lab = mask[idx];
    const float4* ep = emb + (((size_t)b * E_) << N4SHIFT) + n4;

    const float* cx = &csh[lab.x * 17];
    const float* cy = &csh[lab.y * 17];
    const float* cz = &csh[lab.z * 17];
    const float* cw = &csh[lab.w * 17];

    float ssx = 0.f, ssy = 0.f, ssz = 0.f, ssw = 0.f;
#pragma unroll
    for (int e = 0; e < E_; e++) {
        float4 q = ep[(size_t)e << N4SHIFT];
        float dx = q.x - cx[e]; ssx = fmaf(dx, dx, ssx);
        float dy = q.y - cy[e]; ssy = fmaf(dy, dy, ssy);
        float dz = q.z - cz[e]; ssz = fmaf(dz, dz, ssz);
        float dw = q.w - cw[e]; ssw = fmaf(dw, dw, ssw);
    }
    if (lab.x > 0 && lab.x <= CMAX) { float h = sqrtf(ssx) - DVAR; if (h > 0.f) red_add(&g_hinge[b * CS + lab.x], h * h); }
    if (lab.y > 0 && lab.y <= CMAX) { float h = sqrtf(ssy) - DVAR; if (h > 0.f) red_add(&g_hinge[b * CS + lab.y], h * h); }
    if (lab.z > 0 && lab.z <= CMAX) { float h = sqrtf(ssz) - DVAR; if (h > 0.f) red_add(&g_hinge[b * CS + lab.z], h * h); }
    if (lab.w > 0 && lab.w <= CMAX) { float h = sqrtf(ssw) - DVAR; if (h > 0.f) red_add(&g_hinge[b * CS + lab.w], h * h); }
}

// ---------------- Finalize: var/dist/reg terms + batch reduction ----------------
// One block, 256 threads; warp w handles batch b=w, lane c handles class c+1.
__global__ void __launch_bounds__(256) k_final(const int* __restrict__ ninst,
                                               float* __restrict__ out, int out_size) {
    __shared__ float cents[B_][CMAX][E_ + 1];
    __shared__ float part[B_][4];
    int C = *ninst; if (C > CMAX) C = CMAX;
    int lane = threadIdx.x & 31;
    int b = threadIdx.x >> 5;

    float cnt = 0.f;
    if (lane < C) cnt = g_cnt[b * CS + lane + 1];
    bool pres = cnt > 0.f;
    float safe = fmaxf(cnt, 1.f);

    float ce[E_];
    float ss = 0.f;
#pragma unroll
    for (int e = 0; e < E_; e++) {
        float v = (lane < C) ? g_sums[(b * CS + lane + 1) * E_ + e] / safe : 0.f;
        ce[e] = v;
        cents[b][lane][e] = v;
        ss = fmaf(v, v, ss);
    }
    unsigned pmask = __ballot_sync(0xffffffffu, pres);
    int npres = __popc(pmask);
    float hv = pres ? g_hinge[b * CS + lane + 1] / safe : 0.f;
    float rg = pres ? sqrtf(ss) : 0.f;
    __syncwarp();

    float ph = 0.f, np = 0.f;
    if (pres) {
        for (int c2 = lane + 1; c2 < C; c2++) {
            if ((pmask >> c2) & 1u) {
                float pss = 0.f;
#pragma unroll
                for (int e = 0; e < E_; e++) {
                    float d = ce[e] - cents[b][c2][e];
                    pss = fmaf(d, d, pss);
                }
                float h = TWO_DDIST - sqrtf(pss);
                if (h > 0.f) ph += h * h;
                np += 1.f;
            }
        }
    }
    hv = wred(hv); rg = wred(rg); ph = wred(ph); np = wred(np);

    if (lane == 0) {
        float nv = (float)npres;
        part[b][0] = (npres > 0) ? hv / nv : 0.f;
        part[b][1] = (np > 0.f) ? ph / np : 0.f;
        part[b][2] = (npres > 0) ? rg / nv : 0.f;
        part[b][3] = (npres > 0) ? 1.f : 0.f;
    }
    __syncthreads();
    if (threadIdx.x == 0) {
        float sv = 0.f, sd = 0.f, sr = 0.f, vb = 0.f;
        for (int bb = 0; bb < B_; bb++) {
            sv += part[bb][0] * part[bb][3];
            sd += part[bb][1] * part[bb][3];
            sr += part[bb][2] * part[bb][3];
            vb += part[bb][3];
        }
        float den = fmaxf(vb, 1.f);
        float lv = (vb > 0.f) ? sv / den : 0.f;
        float ld = (vb > 0.f) ? sd / den : 0.f;
        float lr = (vb > 0.f) ? sr / den : 0.f;
        float tot = lv + ld + GAMMA_ * lr;
        out[0] = tot;
        if (out_size > 1) out[1] = lv;
        if (out_size > 2) out[2] = ld;
        if (out_size > 3) out[3] = lr;
    }
}

extern "C" void kernel_launch(void* const* d_in, const int* in_sizes, int n_in,
                              void* d_out, int out_size) {
    const float* emb = (const float*)d_in[0];
    const int* mask = (const int*)d_in[1];
    const int* ninst = (const int*)d_in[2];
    (void)in_sizes; (void)n_in;

    int total4 = B_ * N4_;              // 524288 threads, 4 pixels each
    k_zero<<<(B_ * CS * E_ + 255) / 256, 256>>>();
    k_pass1<<<total4 / 256, 256>>>((const float4*)emb, (const int4*)mask);
    k_pass2<<<total4 / 256, 256>>>((const float4*)emb, (const int4*)mask);
    k_final<<<1, 256>>>(ninst, (float*)d_out, out_size);
}

// round 4
// speedup vs baseline: 5.0441x; 5.0441x over previous
#include <cuda_runtime.h>

// DiscriminativeLoss: B=8, E=16, N=512*512, C<=32
// Privatized-atomics version: per-block scratch slots kill L2 same-address
// serialization (the R1 bottleneck).
// K0 zero scratch -> K1 pass1 (segment sums into private slots)
// -> K2 reduce slots to centers -> K3 pass2 (hinge into private slots)
// -> K4 finalize.

namespace {
constexpr int B_ = 8;
constexpr int E_ = 16;
constexpr int N_ = 512 * 512;
constexpr int N4_ = N_ / 4;       // 65536 float4 groups per batch
constexpr int N4SHIFT = 16;
constexpr int CMAX = 32;
constexpr int CS = 33;            // labels 0..32 (0 = background)
constexpr int P1BLK_PER_B = 64;   // pass1 blocks per batch
constexpr int P1SLOTS = B_ * P1BLK_PER_B;       // 512
constexpr int P2BLK_PER_B = 256;  // pass2 blocks per batch
constexpr int P2SLOTS = B_ * P2BLK_PER_B;       // 2048
constexpr float DVAR = 0.5f;
constexpr float TWO_DDIST = 3.0f;
constexpr float GAMMA_ = 0.001f;
}

// Per-block private accumulators (contention-free)
__device__ float g_psums[P1SLOTS * CS * E_];  // 270336 floats
__device__ float g_pcnt[P1SLOTS * CS];        // 16896
__device__ float g_phinge[P2SLOTS * CS];      // 67584
// Reduced results
__device__ float g_centers[B_ * CS * E_];
__device__ float g_cnt[B_ * CS];

__device__ __forceinline__ void red_add_v4(float* a, float x, float y, float z, float w) {
    asm volatile("red.global.add.v4.f32 [%0], {%1,%2,%3,%4};"
                 :: "l"(a), "f"(x), "f"(y), "f"(z), "f"(w) : "memory");
}
__device__ __forceinline__ void red_add(float* a, float v) {
    asm volatile("red.global.add.f32 [%0], %1;" :: "l"(a), "f"(v) : "memory");
}
__device__ __forceinline__ float wred(float v) {
#pragma unroll
    for (int o = 16; o; o >>= 1) v += __shfl_xor_sync(0xffffffffu, v, o);
    return v;
}

__global__ void k_zero() {
    int i = blockIdx.x * blockDim.x + threadIdx.x;
    if (i < P1SLOTS * CS * E_) g_psums[i] = 0.f;
    if (i < P1SLOTS * CS) g_pcnt[i] = 0.f;
    if (i < P2SLOTS * CS) g_phinge[i] = 0.f;
}

// ---------------- Pass 1: segment sums + counts (private slots) ----------------
// 512 blocks x 256 threads; each thread handles 4 groups of 4 pixels.
__global__ void __launch_bounds__(256) k_pass1(const float4* __restrict__ emb,
                                               const int4* __restrict__ mask) {
    int b = blockIdx.x >> 6;          // 64 blocks per batch
    int chunk = blockIdx.x & 63;
    float* slot_sums = &g_psums[blockIdx.x * CS * E_];
    float* slot_cnt = &g_pcnt[blockIdx.x * CS];

#pragma unroll
    for (int grp = 0; grp < 4; grp++) {
        int n4 = (chunk << 10) + (grp << 8) + threadIdx.x;
        int4 lab = mask[(b << N4SHIFT) + n4];
        const float4* ep = emb + (((size_t)b * E_) << N4SHIFT) + n4;

        bool vx = lab.x > 0;
        bool vy = lab.y > 0;
        bool vz = lab.z > 0;
        bool vw = lab.w > 0;
        float* bx = slot_sums + lab.x * E_;
        float* by = slot_sums + lab.y * E_;
        float* bz = slot_sums + lab.z * E_;
        float* bw = slot_sums + lab.w * E_;

#pragma unroll
        for (int g = 0; g < 4; g++) {
            float4 q0 = ep[(size_t)(4 * g + 0) << N4SHIFT];
            float4 q1 = ep[(size_t)(4 * g + 1) << N4SHIFT];
            float4 q2 = ep[(size_t)(4 * g + 2) << N4SHIFT];
            float4 q3 = ep[(size_t)(4 * g + 3) << N4SHIFT];
            if (vx) red_add_v4(bx + 4 * g, q0.x, q1.x, q2.x, q3.x);
            if (vy) red_add_v4(by + 4 * g, q0.y, q1.y, q2.y, q3.y);
            if (vz) red_add_v4(bz + 4 * g, q0.z, q1.z, q2.z, q3.z);
            if (vw) red_add_v4(bw + 4 * g, q0.w, q1.w, q2.w, q3.w);
        }
        if (vx) red_add(slot_cnt + lab.x, 1.f);
        if (vy) red_add(slot_cnt + lab.y, 1.f);
        if (vz) red_add(slot_cnt + lab.z, 1.f);
        if (vw) red_add(slot_cnt + lab.w, 1.f);
    }
}

// ---------------- Reduce slots -> counts + centers (divide fused) ----------------
// 8 blocks (one per batch) x 544 threads.
__global__ void __launch_bounds__(544) k_reduce() {
    __shared__ float scnt[CS];
    int b = blockIdx.x;
    int t = threadIdx.x;
    if (t < CS) {
        float c = 0.f;
        for (int s = 0; s < P1BLK_PER_B; s++)
            c += g_pcnt[(b * P1BLK_PER_B + s) * CS + t];
        scnt[t] = c;
        g_cnt[b * CS + t] = c;
    }
    __syncthreads();
    if (t < CS * E_) {
        int l = t >> 4, e = t & 15;
        float ssum = 0.f;
        for (int s = 0; s < P1BLK_PER_B; s++)
            ssum += g_psums[((b * P1BLK_PER_B + s) * CS + l) * E_ + e];
        g_centers[(b * CS + l) * E_ + e] = ssum / fmaxf(scnt[l], 1.f);
    }
}

// ---------------- Pass 2: hinged variance (private hinge slots) ----------------
// 2048 blocks x 256 threads, 4 pixels/thread. Centers staged in shared,
// stride-17 so distinct labels hit distinct banks.
__global__ void __launch_bounds__(256) k_pass2(const float4* __restrict__ emb,
                                               const int4* __restrict__ mask) {
    __shared__ float csh[CS * 17];
    int idx = blockIdx.x * blockDim.x + threadIdx.x;
    int b = idx >> N4SHIFT;           // constant per block
    float* slot_hinge = &g_phinge[blockIdx.x * CS];

    for (int i = threadIdx.x; i < CS * E_; i += blockDim.x) {
        int l = i >> 4, e = i & 15;
        csh[l * 17 + e] = g_centers[(b * CS + l) * E_ + e];
    }
    __syncthreads();

    int n4 = idx & (N4_ - 1);
    int4 lab = mask[idx];
    const float4* ep = emb + (((size_t)b * E_) << N4SHIFT) + n4;

    const float* cx = &csh[lab.x * 17];
    const float* cy = &csh[lab.y * 17];
    const float* cz = &csh[lab.z * 17];
    const float* cw = &csh[lab.w * 17];

    float ssx = 0.f, ssy = 0.f, ssz = 0.f, ssw = 0.f;
#pragma unroll
    for (int e = 0; e < E_; e++) {
        float4 q = ep[(size_t)e << N4SHIFT];
        float dx = q.x - cx[e]; ssx = fmaf(dx, dx, ssx);
        float dy = q.y - cy[e]; ssy = fmaf(dy, dy, ssy);
        float dz = q.z - cz[e]; ssz = fmaf(dz, dz, ssz);
        float dw = q.w - cw[e]; ssw = fmaf(dw, dw, ssw);
    }
    if (lab.x > 0) { float h = sqrtf(ssx) - DVAR; if (h > 0.f) red_add(slot_hinge + lab.x, h * h); }
    if (lab.y > 0) { float h = sqrtf(ssy) - DVAR; if (h > 0.f) red_add(slot_hinge + lab.y, h * h); }
    if (lab.z > 0) { float h = sqrtf(ssz) - DVAR; if (h > 0.f) red_add(slot_hinge + lab.z, h * h); }
    if (lab.w > 0) { float h = sqrtf(ssw) - DVAR; if (h > 0.f) red_add(slot_hinge + lab.w, h * h); }
}

// ---------------- Finalize ----------------
// 1 block, 256 threads; warp b handles batch b, lane c handles class c+1.
__global__ void __launch_bounds__(256) k_final(const int* __restrict__ ninst,
                                               float* __restrict__ out, int out_size) {
    __shared__ float cents[B_][CMAX][E_ + 1];
    __shared__ float part[B_][4];
    int C = *ninst; if (C > CMAX) C = CMAX;
    int lane = threadIdx.x & 31;
    int b = threadIdx.x >> 5;

    float cnt = 0.f;
    if (lane < C) cnt = g_cnt[b * CS + lane + 1];
    bool pres = cnt > 0.f;
    float safe = fmaxf(cnt, 1.f);

    float ce[E_];
    float ss = 0.f;
#pragma unroll
    for (int e = 0; e < E_; e++) {
        float v = (lane < C) ? g_centers[(b * CS + lane + 1) * E_ + e] : 0.f;
        ce[e] = v;
        cents[b][lane][e] = v;
        ss = fmaf(v, v, ss);
    }
    unsigned pmask = __ballot_sync(0xffffffffu, pres);
    int npres = __popc(pmask);

    // fold private hinge slots for this (b, class)
    float hv = 0.f;
    if (pres) {
        int base = b * P2BLK_PER_B;
#pragma unroll 8
        for (int s = 0; s < P2BLK_PER_B; s++)
            hv += g_phinge[(base + s) * CS + lane + 1];
        hv /= safe;
    }
    float rg = pres ? sqrtf(ss) : 0.f;
    __syncwarp();

    float ph = 0.f, np = 0.f;
    if (pres) {
        for (int c2 = lane + 1; c2 < C; c2++) {
            if ((pmask >> c2) & 1u) {
                float pss = 0.f;
#pragma unroll
                for (int e = 0; e < E_; e++) {
                    float d = ce[e] - cents[b][c2][e];
                    pss = fmaf(d, d, pss);
                }
                float h = TWO_DDIST - sqrtf(pss);
                if (h > 0.f) ph += h * h;
                np += 1.f;
            }
        }
    }
    hv = wred(hv); rg = wred(rg); ph = wred(ph); np = wred(np);

    if (lane == 0) {
        float nv = (float)npres;
        part[b][0] = (npres > 0) ? hv / nv : 0.f;
        part[b][1] = (np > 0.f) ? ph / np : 0.f;
        part[b][2] = (npres > 0) ? rg / nv : 0.f;
        part[b][3] = (npres > 0) ? 1.f : 0.f;
    }
    __syncthreads();
    if (threadIdx.x == 0) {
        float sv = 0.f, sd = 0.f, sr = 0.f, vb = 0.f;
        for (int bb = 0; bb < B_; bb++) {
            sv += part[bb][0] * part[bb][3];
            sd += part[bb][1] * part[bb][3];
            sr += part[bb][2] * part[bb][3];
            vb += part[bb][3];
        }
        float den = fmaxf(vb, 1.f);
        float lv = (vb > 0.f) ? sv / den : 0.f;
        float ld = (vb > 0.f) ? sd / den : 0.f;
        float lr = (vb > 0.f) ? sr / den : 0.f;
        float tot = lv + ld + GAMMA_ * lr;
        out[0] = tot;
        if (out_size > 1) out[1] = lv;
        if (out_size > 2) out[2] = ld;
        if (out_size > 3) out[3] = lr;
    }
}

extern "C" void kernel_launch(void* const* d_in, const int* in_sizes, int n_in,
                              void* d_out, int out_size) {
    const float* emb = (const float*)d_in[0];
    const int* mask = (const int*)d_in[1];
    const int* ninst = (const int*)d_in[2];
    (void)in_sizes; (void)n_in;

    k_zero<<<(P1SLOTS * CS * E_ + 255) / 256, 256>>>();
    k_pass1<<<P1SLOTS, 256>>>((const float4*)emb, (const int4*)mask);
    k_reduce<<<B_, 544>>>();
    k_pass2<<<P2SLOTS, 256>>>((const float4*)emb, (const int4*)mask);
    k_final<<<1, 256>>>(ninst, (float*)d_out, out_size);
}

// round 5
// speedup vs baseline: 6.9909x; 1.3859x over previous
#include <cuda_runtime.h>

// DiscriminativeLoss: B=8, E=16, N=512*512, C<=32
// R4: pass1 rewritten as per-tile counting sort + SMEM gather to kill the
// L2 atomic-ALU bottleneck (33.6M f32 adds -> ~1.1M).
// K0 zero (tiny) -> K1 pass1 (persistent, cp.async double-buffered, sorted
// accumulation) -> K2 pass2 (hinge, shared-folded) -> K3 finalize.

namespace {
constexpr int B_ = 8;
constexpr int E_ = 16;
constexpr int NSHIFT = 18;        // N = 2^18
constexpr int N_ = 1 << NSHIFT;
constexpr int N4_ = N_ / 4;
constexpr int N4SHIFT = 16;
constexpr int CMAX = 32;
constexpr int CS = 33;
constexpr float DVAR = 0.5f;
constexpr float TWO_DDIST = 3.0f;
constexpr float GAMMA_ = 0.001f;

// pass1 tiling
constexpr int TPX = 1024;                    // pixels per tile
constexpr int ESTRIDE = 1028;                // padded floats per dim row
constexpr int T1 = 512;                      // pass1 threads
constexpr int NTILES = B_ * N_ / TPX;        // 2048
constexpr int TILES_PER_B = N_ / TPX;        // 256
constexpr int GRID1 = 148;
// dynamic smem layout (in floats / bytes)
constexpr int EMB_BUF_F = E_ * ESTRIDE;      // 16448 floats per buffer
constexpr int LAB_OFF_F = 2 * EMB_BUF_F;     // labels after 2 emb buffers
constexpr int SORT_OFF_F = LAB_OFF_F + 2 * TPX;       // after 2 int label buffers
// sorted u16[TPX] = 512 floats, then hist/soff/scur ints
constexpr int HIST_OFF_F = SORT_OFF_F + TPX / 2;
constexpr int SMEM1_FLOATS = HIST_OFF_F + 3 * CS + 8;
constexpr int SMEM1_BYTES = SMEM1_FLOATS * 4;          // ~142.6 KB
}

__device__ __align__(16) float g_sums[B_ * CS * E_];
__device__ float g_cnt[B_ * CS];
__device__ float g_hinge[B_ * CS];

__device__ __forceinline__ void red_add_v4(float* a, float x, float y, float z, float w) {
    asm volatile("red.global.add.v4.f32 [%0], {%1,%2,%3,%4};"
                 :: "l"(a), "f"(x), "f"(y), "f"(z), "f"(w) : "memory");
}
__device__ __forceinline__ void red_add(float* a, float v) {
    asm volatile("red.global.add.f32 [%0], %1;" :: "l"(a), "f"(v) : "memory");
}
__device__ __forceinline__ void cp16(unsigned dst, const void* src) {
    asm volatile("cp.async.cg.shared.global [%0], [%1], 16;" :: "r"(dst), "l"(src));
}
__device__ __forceinline__ unsigned smem_u32(const void* p) {
    unsigned a;
    asm("{ .reg .u64 t; cvta.to.shared.u64 t, %1; cvt.u32.u64 %0, t; }" : "=r"(a) : "l"(p));
    return a;
}
__device__ __forceinline__ float wred(float v) {
#pragma unroll
    for (int o = 16; o; o >>= 1) v += __shfl_xor_sync(0xffffffffu, v, o);
    return v;
}

__global__ void k_zero() {
    int i = threadIdx.x;
    for (; i < B_ * CS * E_; i += blockDim.x) g_sums[i] = 0.f;
    i = threadIdx.x;
    if (i < B_ * CS) { g_cnt[i] = 0.f; g_hinge[i] = 0.f; }
}

// ---------------- Pass 1: sorted segment sums ----------------
__global__ void __launch_bounds__(T1) k_pass1(const float* __restrict__ emb,
                                              const int* __restrict__ mask) {
    extern __shared__ float sm[];
    float* embS = sm;                                   // [2][16][1028]
    int* labS = (int*)(sm + LAB_OFF_F);                 // [2][1024]
    unsigned short* sortedS = (unsigned short*)(sm + SORT_OFF_F);  // [1024]
    int* shist = (int*)(sm + HIST_OFF_F);               // [33]
    int* soff = shist + CS;                             // [33]
    int* scur = soff + CS;                              // [33]

    const int tid = threadIdx.x;
    const int lane = tid & 31;
    const int wid = tid >> 5;
    const unsigned smem_base = smem_u32(sm);

    // tiles owned by this block
    const int t0 = blockIdx.x;

    // prefetch helper (inlined via lambda-like macro logic)
    auto prefetch = [&](int t, int buf) {
        int b = t >> 8;                       // TILES_PER_B = 256
        int gp0 = (t & (TILES_PER_B - 1)) << 10;
        const float* ebase = emb + (((size_t)b * E_) << NSHIFT) + gp0;
#pragma unroll
        for (int k = 0; k < 8; k++) {
            int c = tid + k * T1;             // 0..4095
            int e = c >> 8, i4 = (c & 255) << 2;
            cp16(smem_base + (unsigned)(buf * EMB_BUF_F + e * ESTRIDE + i4) * 4u,
                 ebase + ((size_t)e << NSHIFT) + i4);
        }
        const int* lbase = mask + ((size_t)b << NSHIFT) + gp0;
        if (tid < 256)
            cp16(smem_base + (unsigned)(LAB_OFF_F + buf * TPX + tid * 4) * 4u,
                 lbase + tid * 4);
        asm volatile("cp.async.commit_group;" ::: "memory");
    };

    int nt = 0;
    for (int t = t0; t < NTILES; t += GRID1) nt++;
    if (nt == 0) return;

    prefetch(t0, 0);

    for (int k = 0; k < nt; k++) {
        int t = t0 + k * GRID1;
        int buf = k & 1;
        bool more = (k + 1) < nt;
        if (more) prefetch(t + GRID1, buf ^ 1);
        if (more) { asm volatile("cp.async.wait_group 1;" ::: "memory"); }
        else      { asm volatile("cp.async.wait_group 0;" ::: "memory"); }
        __syncthreads();

        int b = t >> 8;
        const int* lab = labS + buf * TPX;
        const float* eb = embS + buf * EMB_BUF_F;

        // 1. zero hist
        if (tid < CS) shist[tid] = 0;
        __syncthreads();
        // 2. histogram (2 px per thread)
        int l0 = lab[tid], l1 = lab[tid + T1];
        if (l0 > 0) atomicAdd(&shist[l0], 1);
        if (l1 > 0) atomicAdd(&shist[l1], 1);
        __syncthreads();
        // 3. scan + count REDs (warp 0; labels 1..32 on lanes 0..31)
        if (wid == 0) {
            int c = shist[lane + 1];
            int inc = c;
#pragma unroll
            for (int o = 1; o < 32; o <<= 1) {
                int v = __shfl_up_sync(0xffffffffu, inc, o);
                if (lane >= o) inc += v;
            }
            int start = inc - c;
            soff[lane + 1] = start;
            scur[lane + 1] = start;
            if (c > 0) red_add(&g_cnt[b * CS + lane + 1], (float)c);
        }
        __syncthreads();
        // 4. scatter
        if (l0 > 0) { int p = atomicAdd(&scur[l0], 1); sortedS[p] = (unsigned short)tid; }
        if (l1 > 0) { int p = atomicAdd(&scur[l1], 1); sortedS[p] = (unsigned short)(tid + T1); }
        __syncthreads();
        // 5. gather + accumulate: warp w owns labels 2w+1, 2w+2
#pragma unroll
        for (int li = 0; li < 2; li++) {
            int l = 2 * wid + 1 + li;
            int m = shist[l];
            int start = soff[l];
            float acc[E_];
#pragma unroll
            for (int e = 0; e < E_; e++) acc[e] = 0.f;
            for (int p = lane; p < m; p += 32) {
                int idx = sortedS[start + p];
                const float* px = eb + idx;
#pragma unroll
                for (int e = 0; e < E_; e++) acc[e] += px[e * ESTRIDE];
            }
#pragma unroll
            for (int o = 16; o; o >>= 1) {
#pragma unroll
                for (int e = 0; e < E_; e++)
                    acc[e] += __shfl_xor_sync(0xffffffffu, acc[e], o);
            }
            if (lane == 0 && m > 0) {
                float* dst = &g_sums[(b * CS + l) * E_];
                red_add_v4(dst + 0, acc[0], acc[1], acc[2], acc[3]);
                red_add_v4(dst + 4, acc[4], acc[5], acc[6], acc[7]);
                red_add_v4(dst + 8, acc[8], acc[9], acc[10], acc[11]);
                red_add_v4(dst + 12, acc[12], acc[13], acc[14], acc[15]);
            }
        }
        __syncthreads();   // protect sort arrays + emb buffer for reuse
    }
}

// ---------------- Pass 2: hinged variance (shared-folded) ----------------
__global__ void __launch_bounds__(256) k_pass2(const float4* __restrict__ emb,
                                               const int4* __restrict__ mask) {
    __shared__ float csh[CS * 17];
    __shared__ float shinge[CS];
    int idx = blockIdx.x * blockDim.x + threadIdx.x;
    int b = idx >> N4SHIFT;   // constant per block

    if (threadIdx.x < CS) shinge[threadIdx.x] = 0.f;
    for (int i = threadIdx.x; i < CS * E_; i += blockDim.x) {
        int l = i >> 4, e = i & 15;
        csh[l * 17 + e] = g_sums[(b * CS + l) * E_ + e] / fmaxf(g_cnt[b * CS + l], 1.f);
    }
    __syncthreads();

    int n4 = idx & (N4_ - 1);
    int4 lab = mask[idx];
    const float4* ep = emb + (((size_t)b * E_) << N4SHIFT) + n4;

    const float* cx = &csh[lab.x * 17];
    const float* cy = &csh[lab.y * 17];
    const float* cz = &csh[lab.z * 17];
    const float* cw = &csh[lab.w * 17];

    float ssx = 0.f, ssy = 0.f, ssz = 0.f, ssw = 0.f;
#pragma unroll
    for (int e = 0; e < E_; e++) {
        float4 q = ep[(size_t)e << N4SHIFT];
        float dx = q.x - cx[e]; ssx = fmaf(dx, dx, ssx);
        float dy = q.y - cy[e]; ssy = fmaf(dy, dy, ssy);
        float dz = q.z - cz[e]; ssz = fmaf(dz, dz, ssz);
        float dw = q.w - cw[e]; ssw = fmaf(dw, dw, ssw);
    }
    if (lab.x > 0) { float h = sqrtf(ssx) - DVAR; if (h > 0.f) atomicAdd(&shinge[lab.x], h * h); }
    if (lab.y > 0) { float h = sqrtf(ssy) - DVAR; if (h > 0.f) atomicAdd(&shinge[lab.y], h * h); }
    if (lab.z > 0) { float h = sqrtf(ssz) - DVAR; if (h > 0.f) atomicAdd(&shinge[lab.z], h * h); }
    if (lab.w > 0) { float h = sqrtf(ssw) - DVAR; if (h > 0.f) atomicAdd(&shinge[lab.w], h * h); }
    __syncthreads();
    if (threadIdx.x < CS && shinge[threadIdx.x] != 0.f)
        red_add(&g_hinge[b * CS + threadIdx.x], shinge[threadIdx.x]);
}

// ---------------- Finalize ----------------
__global__ void __launch_bounds__(256) k_final(const int* __restrict__ ninst,
                                               float* __restrict__ out, int out_size) {
    __shared__ float cents[B_][CMAX][E_ + 1];
    __shared__ float part[B_][4];
    int C = *ninst; if (C > CMAX) C = CMAX;
    int lane = threadIdx.x & 31;
    int b = threadIdx.x >> 5;

    float cnt = 0.f;
    if (lane < C) cnt = g_cnt[b * CS + lane + 1];
    bool pres = cnt > 0.f;
    float safe = fmaxf(cnt, 1.f);

    float ce[E_];
    float ss = 0.f;
#pragma unroll
    for (int e = 0; e < E_; e++) {
        float v = (lane < C) ? g_sums[(b * CS + lane + 1) * E_ + e] / safe : 0.f;
        ce[e] = v;
        cents[b][lane][e] = v;
        ss = fmaf(v, v, ss);
    }
    unsigned pmask = __ballot_sync(0xffffffffu, pres);
    int npres = __popc(pmask);
    float hv = pres ? g_hinge[b * CS + lane + 1] / safe : 0.f;
    float rg = pres ? sqrtf(ss) : 0.f;
    __syncwarp();

    float ph = 0.f, np = 0.f;
    if (pres) {
        for (int c2 = lane + 1; c2 < C; c2++) {
            if ((pmask >> c2) & 1u) {
                float pss = 0.f;
#pragma unroll
                for (int e = 0; e < E_; e++) {
                    float d = ce[e] - cents[b][c2][e];
                    pss = fmaf(d, d, pss);
                }
                float h = TWO_DDIST - sqrtf(pss);
                if (h > 0.f) ph += h * h;
                np += 1.f;
            }
        }
    }
    hv = wred(hv); rg = wred(rg); ph = wred(ph); np = wred(np);

    if (lane == 0) {
        float nv = (float)npres;
        part[b][0] = (npres > 0) ? hv / nv : 0.f;
        part[b][1] = (np > 0.f) ? ph / np : 0.f;
        part[b][2] = (npres > 0) ? rg / nv : 0.f;
        part[b][3] = (npres > 0) ? 1.f : 0.f;
    }
    __syncthreads();
    if (threadIdx.x == 0) {
        float sv = 0.f, sd = 0.f, sr = 0.f, vb = 0.f;
        for (int bb = 0; bb < B_; bb++) {
            sv += part[bb][0] * part[bb][3];
            sd += part[bb][1] * part[bb][3];
            sr += part[bb][2] * part[bb][3];
            vb += part[bb][3];
        }
        float den = fmaxf(vb, 1.f);
        float lv = (vb > 0.f) ? sv / den : 0.f;
        float ld = (vb > 0.f) ? sd / den : 0.f;
        float lr = (vb > 0.f) ? sr / den : 0.f;
        float tot = lv + ld + GAMMA_ * lr;
        out[0] = tot;
        if (out_size > 1) out[1] = lv;
        if (out_size > 2) out[2] = ld;
        if (out_size > 3) out[3] = lr;
    }
}

extern "C" void kernel_launch(void* const* d_in, const int* in_sizes, int n_in,
                              void* d_out, int out_size) {
    const float* emb = (const float*)d_in[0];
    const int* mask = (const int*)d_in[1];
    const int* ninst = (const int*)d_in[2];
    (void)in_sizes; (void)n_in;

    cudaFuncSetAttribute(k_pass1, cudaFuncAttributeMaxDynamicSharedMemorySize, SMEM1_BYTES);

    k_zero<<<1, 512>>>();
    k_pass1<<<GRID1, T1, SMEM1_BYTES>>>(emb, mask);
    k_pass2<<<B_ * N4_ / 256, 256>>>((const float4*)emb, (const int4*)mask);
    k_final<<<1, 256>>>(ninst, (float*)d_out, out_size);
}